// round 4
// baseline (speedup 1.0000x reference)
#include <cuda_runtime.h>
#include <math.h>

typedef unsigned long long ull;

// ---------------- problem constants ----------------
#define NPTS_MAX 200000
#define NB_MAX   220000
#define NC_MAX   98304
#define IMG_ELEMS (4*512*48*64)

#define CVS0 (6.2831853f/512.0f)
#define CVS1 0.125f
#define CR0  (-3.14159265f)
#define CR1  (-2.0f)

// ---------------- scratch ----------------
__device__ float d_lin1[(size_t)NPTS_MAX*64];
__device__ float d_lin2[(size_t)NPTS_MAX*128];
__device__ float d_dense[IMG_ELEMS];
__device__ float d_conv[IMG_ELEMS];
__device__ float d_bevsum[NB_MAX*4];
__device__ float d_cylsum[NC_MAX*4];
__device__ float d_stats[1024];   // lin1@0(s64,s2 64), lin2@128(s128,s2 128), conv@384, lin3@512
__device__ float d_bn[1024];      // lin1 a@0 c@64; lin2 a@128 c@256; conv a@384 c@448; lin3 a@512 c@576
__device__ unsigned d_ctr[8];

// ---------------- f32x2 helpers ----------------
__device__ __forceinline__ ull pk2(float v) {
    ull r; unsigned u = __float_as_uint(v);
    asm("mov.b64 %0, {%1, %1};" : "=l"(r) : "r"(u));
    return r;
}
__device__ __forceinline__ void ffma2(ull& d, ull a, ull b) {
    asm("fma.rn.f32x2 %0, %1, %2, %0;" : "+l"(d) : "l"(a), "l"(b));
}
__device__ __forceinline__ ull add2(ull a, ull b) {
    ull d; asm("add.rn.f32x2 %0, %1, %2;" : "=l"(d) : "l"(a), "l"(b)); return d;
}
__device__ __forceinline__ ull sq2(ull a) {
    ull d; asm("mul.rn.f32x2 %0, %1, %2;" : "=l"(d) : "l"(a), "l"(a)); return d;
}
__device__ __forceinline__ void unpack2(ull v, float& lo, float& hi) {
    asm("mov.b64 {%0, %1}, %2;" : "=f"(lo), "=f"(hi) : "l"(v));
}
__device__ __forceinline__ ull shfl_xor2(ull v, int m) {
    unsigned lo = (unsigned)v, hi = (unsigned)(v >> 32);
    lo = __shfl_xor_sync(0xffffffffu, lo, m);
    hi = __shfl_xor_sync(0xffffffffu, hi, m);
    return ((ull)hi << 32) | (ull)lo;
}
__device__ __forceinline__ ull warp_red2(ull v) {
    #pragma unroll
    for (int st = 16; st; st >>= 1) v = add2(v, shfl_xor2(v, st));
    return v;
}
// last-block finalize: compute a,c BN params from accumulated stats
__device__ __forceinline__ void bn_finalize(int ctr_idx, unsigned nblocks, int tid,
                                            int C, float invn, int sbase, int bbase,
                                            const float* g, const float* b) {
    __threadfence();
    __shared__ unsigned s_ord;
    if (tid == 0) s_ord = atomicAdd(&d_ctr[ctr_idx], 1u);
    __syncthreads();
    if (s_ord == nblocks - 1 && tid < C) {
        float m = __ldcg(&d_stats[sbase + tid]) * invn;
        float v = __ldcg(&d_stats[sbase + C + tid]) * invn - m * m;
        float a = g[tid] * rsqrtf(v + 1e-3f);
        d_bn[bbase + tid]     = a;
        d_bn[bbase + C + tid] = b[tid] - m * a;
    }
}

// ---------------- kernels ----------------
__global__ void __launch_bounds__(256) k_zero(float* outbev, int nb, int nc) {
    size_t tid = (size_t)blockIdx.x * blockDim.x + threadIdx.x;
    size_t stride = (size_t)gridDim.x * blockDim.x;
    float4 z = make_float4(0.f, 0.f, 0.f, 0.f);
    float4* p = (float4*)d_dense;
    for (size_t i = tid; i < IMG_ELEMS/4; i += stride) p[i] = z;
    float4* q = (float4*)outbev;
    size_t obw = (size_t)nb * 16;           // nb*64/4
    for (size_t i = tid; i < obw; i += stride) q[i] = z;
    float4* bs = (float4*)d_bevsum;
    for (size_t i = tid; i < (size_t)nb; i += stride) bs[i] = z;
    float4* cs = (float4*)d_cylsum;
    for (size_t i = tid; i < (size_t)nc; i += stride) cs[i] = z;
    if (tid < 256) ((float4*)d_stats)[tid] = z;
    if (tid < 8) d_ctr[tid] = 0u;
}

__global__ void k_scatter(const float* __restrict__ pts, const float* __restrict__ pcyl,
                          const int* __restrict__ binv, const int* __restrict__ cinv, int n) {
    int i = blockIdx.x*blockDim.x + threadIdx.x;
    if (i >= n) return;
    float x = pts[(size_t)i*5+1], y = pts[(size_t)i*5+2], z = pts[(size_t)i*5+3];
    int bi = binv[i], ci = cinv[i];
    atomicAdd(&d_bevsum[bi*4+0], x);
    atomicAdd(&d_bevsum[bi*4+1], y);
    atomicAdd(&d_bevsum[bi*4+2], z);
    atomicAdd(&d_bevsum[bi*4+3], 1.0f);
    float p0 = pcyl[(size_t)i*3], p1 = pcyl[(size_t)i*3+1], p2 = pcyl[(size_t)i*3+2];
    atomicAdd(&d_cylsum[ci*4+0], p0);
    atomicAdd(&d_cylsum[ci*4+1], p1);
    atomicAdd(&d_cylsum[ci*4+2], p2);
    atomicAdd(&d_cylsum[ci*4+3], 1.0f);
}

__global__ void __launch_bounds__(256) k_lin1(
        const float* __restrict__ pts, const float* __restrict__ pcyl,
        const float* __restrict__ cylidx, const float* __restrict__ bevidx,
        const int* __restrict__ binv, const int* __restrict__ cinv,
        const float* __restrict__ w1, const float* __restrict__ g1,
        const float* __restrict__ b1, int n, float invn) {
    __shared__ float sw[16*64];
    __shared__ float sstat[128];
    int tid = threadIdx.x;
    int lane = tid & 31;
    for (int t = tid; t < 1024; t += 256) { int o = t >> 4, k = t & 15; sw[k*64+o] = w1[t]; }
    if (tid < 128) sstat[tid] = 0.f;
    __syncthreads();
    int i = blockIdx.x*256 + tid;
    bool valid = i < n;
    ull acc[32];
    #pragma unroll
    for (int o = 0; o < 32; o++) acc[o] = 0ULL;
    if (valid) {
        float x = pts[(size_t)i*5+1], y = pts[(size_t)i*5+2], z = pts[(size_t)i*5+3], it = pts[(size_t)i*5+4];
        float phi = pcyl[(size_t)i*3], zc = pcyl[(size_t)i*3+1], rho = pcyl[(size_t)i*3+2];
        float bix = bevidx[2*(size_t)i], biy = bevidx[2*(size_t)i+1];
        float cix = cylidx[2*(size_t)i], ciy = cylidx[2*(size_t)i+1];
        int bi = binv[i], ci = cinv[i];
        float bcnt = d_bevsum[bi*4+3];
        float bmx = d_bevsum[bi*4]/bcnt, bmy = d_bevsum[bi*4+1]/bcnt;
        float ccnt = d_cylsum[ci*4+3];
        float cm0 = d_cylsum[ci*4]/ccnt, cm1 = d_cylsum[ci*4+1]/ccnt;
        float f[16];
        f[0]=x; f[1]=y; f[2]=z; f[3]=phi; f[4]=zc; f[5]=rho;
        f[6] = x - ((floorf(bix)+0.5f)*0.32f + 0.0f);
        f[7] = y - ((floorf(biy)+0.5f)*0.32f + (-40.0f));
        f[8] = phi - ((floorf(cix)+0.5f)*CVS0 + CR0);
        f[9] = zc  - ((floorf(ciy)+0.5f)*CVS1 + CR1);
        f[10]= x - bmx; f[11]= y - bmy;
        f[12]= phi - cm0; f[13]= zc - cm1;
        f[14]= sqrtf(x*x + y*y + z*z);
        f[15]= it;
        #pragma unroll
        for (int k = 0; k < 16; k++) {
            ull v = pk2(f[k]);
            const ulonglong2* wr = (const ulonglong2*)&sw[k*64];
            #pragma unroll
            for (int m = 0; m < 16; m++) {
                ulonglong2 w = wr[m];
                ffma2(acc[2*m], v, w.x); ffma2(acc[2*m+1], v, w.y);
            }
        }
        ulonglong2* op = (ulonglong2*)&d_lin1[(size_t)i*64];
        #pragma unroll
        for (int m = 0; m < 16; m++) op[m] = make_ulonglong2(acc[2*m], acc[2*m+1]);
    }
    // fused stats (all threads participate; invalid contribute zeros)
    #pragma unroll
    for (int m = 0; m < 32; m++) {
        ull s = acc[m];
        ull s2 = sq2(s);
        s = warp_red2(s); s2 = warp_red2(s2);
        if (lane == 0) {
            float a, b;
            unpack2(s, a, b);
            atomicAdd(&sstat[2*m], a); atomicAdd(&sstat[2*m+1], b);
            unpack2(s2, a, b);
            atomicAdd(&sstat[64+2*m], a); atomicAdd(&sstat[64+2*m+1], b);
        }
    }
    __syncthreads();
    if (tid < 128) atomicAdd(&d_stats[tid], sstat[tid]);
    bn_finalize(0, gridDim.x, tid, 64, invn, 0, 0, g1, b1);
}

// lin2: 64 -> 128, fused stats + finalize
__global__ void __launch_bounds__(256) k_lin2(const float* __restrict__ w2,
        const float* __restrict__ g2, const float* __restrict__ b2, int n, float invn) {
    __shared__ float sw2[64*132];
    __shared__ float sa[64], sc[64];
    __shared__ float sstat[256];
    int tid = threadIdx.x;
    for (int t = tid; t < 8192; t += 256) { int o = t >> 6, k = t & 63; sw2[k*132+o] = w2[t]; }
    if (tid < 64) { sa[tid] = d_bn[tid]; sc[tid] = d_bn[64+tid]; }
    sstat[tid] = 0.f;
    __syncthreads();
    int w = tid >> 5, lane = tid & 31;
    int q = w & 3, g = w >> 2;
    int gp = blockIdx.x*64 + g*32 + lane;
    int p0 = 2*gp;
    bool vld = p0 < n;
    bool ok1 = (p0+1) < n;
    int p1 = ok1 ? p0+1 : p0;
    ull acc0[16], acc1[16];
    #pragma unroll
    for (int j = 0; j < 16; j++) { acc0[j]=0ULL; acc1[j]=0ULL; }
    if (vld) {
        const float4* h0 = (const float4*)&d_lin1[(size_t)p0*64];
        const float4* h1 = (const float4*)&d_lin1[(size_t)p1*64];
        #pragma unroll 4
        for (int kk = 0; kk < 16; kk++) {
            float4 a = h0[kk], b = h1[kk];
            int kb = kk*4;
            float av[4] = {a.x,a.y,a.z,a.w};
            float bv[4] = {b.x,b.y,b.z,b.w};
            #pragma unroll
            for (int j = 0; j < 4; j++) {
                int k = kb + j;
                ull v0 = pk2(fmaxf(fmaf(av[j], sa[k], sc[k]), 0.f));
                ull v1 = pk2(fmaxf(fmaf(bv[j], sa[k], sc[k]), 0.f));
                const ulonglong2* wp = (const ulonglong2*)&sw2[k*132 + q*32];
                #pragma unroll
                for (int m = 0; m < 8; m++) {
                    ulonglong2 wv = wp[m];
                    ffma2(acc0[2*m],   v0, wv.x); ffma2(acc0[2*m+1], v0, wv.y);
                    ffma2(acc1[2*m],   v1, wv.x); ffma2(acc1[2*m+1], v1, wv.y);
                }
            }
        }
        ulonglong2* o0 = (ulonglong2*)&d_lin2[(size_t)p0*128 + q*32];
        #pragma unroll
        for (int m = 0; m < 8; m++) o0[m] = make_ulonglong2(acc0[2*m], acc0[2*m+1]);
        if (ok1) {
            ulonglong2* o1 = (ulonglong2*)&d_lin2[(size_t)p1*128 + q*32];
            #pragma unroll
            for (int m = 0; m < 8; m++) o1[m] = make_ulonglong2(acc1[2*m], acc1[2*m+1]);
        }
    }
    #pragma unroll
    for (int m = 0; m < 16; m++) {
        ull s = 0ULL, s2 = 0ULL;
        if (vld) {
            s = acc0[m]; s2 = sq2(acc0[m]);
            if (ok1) { s = add2(s, acc1[m]); s2 = add2(s2, sq2(acc1[m])); }
        }
        s = warp_red2(s); s2 = warp_red2(s2);
        if (lane == 0) {
            int ch = q*32 + 2*m;
            float a, b;
            unpack2(s, a, b);
            atomicAdd(&sstat[ch], a); atomicAdd(&sstat[ch+1], b);
            unpack2(s2, a, b);
            atomicAdd(&sstat[128+ch], a); atomicAdd(&sstat[128+ch+1], b);
        }
    }
    __syncthreads();
    atomicAdd(&d_stats[128+tid], sstat[tid]);
    bn_finalize(1, gridDim.x, tid, 128, invn, 128, 128, g2, b2);
}

// segment-max of bn_relu(lin2[:, :64]) into dense image
__global__ void k_cylmax(const float* __restrict__ pts, const float* __restrict__ cylidx, int n) {
    __shared__ float sa[64], sc[64];
    if (threadIdx.x < 64) { sa[threadIdx.x] = d_bn[128+threadIdx.x]; sc[threadIdx.x] = d_bn[256+threadIdx.x]; }
    __syncthreads();
    int i = blockIdx.x*blockDim.x + threadIdx.x;
    if (i >= n) return;
    int b = (int)pts[(size_t)i*5];
    int iy = (int)floorf(cylidx[2*(size_t)i]);   iy = max(0, min(iy, 511));
    int ix = (int)floorf(cylidx[2*(size_t)i+1]); ix = max(0, min(ix, 47));
    unsigned* dst = (unsigned*)&d_dense[(((size_t)b*512 + iy)*48 + ix)*64];
    const float4* src = (const float4*)&d_lin2[(size_t)i*128];
    #pragma unroll
    for (int j = 0; j < 16; j++) {
        float4 v = src[j];
        int c = j*4;
        float r0 = fmaxf(fmaf(v.x, sa[c+0], sc[c+0]), 0.f);
        float r1 = fmaxf(fmaf(v.y, sa[c+1], sc[c+1]), 0.f);
        float r2 = fmaxf(fmaf(v.z, sa[c+2], sc[c+2]), 0.f);
        float r3 = fmaxf(fmaf(v.w, sa[c+3], sc[c+3]), 0.f);
        atomicMax(dst+c+0, __float_as_uint(r0));
        atomicMax(dst+c+1, __float_as_uint(r1));
        atomicMax(dst+c+2, __float_as_uint(r2));
        atomicMax(dst+c+3, __float_as_uint(r3));
    }
}

// 3x3 SAME conv, 64->64, fused stats + finalize
#define CTX 16
#define CTY 8
#define HPOS ((CTY+2)*(CTX+2))
#define WPITCH 68
#define IPITCH 65
#define CONV_SMEM ((576*WPITCH + HPOS*IPITCH + 128)*4)
__global__ void __launch_bounds__(256) k_conv(const float* __restrict__ wc,
        const float* __restrict__ gc, const float* __restrict__ bc) {
    extern __shared__ float dsm[];
    float* s_w  = dsm;
    float* s_in = dsm + 576*WPITCH;
    float* sstat = dsm + 576*WPITCH + HPOS*IPITCH;
    int x0 = blockIdx.x*CTX, y0 = blockIdx.y*CTY, bb = blockIdx.z;
    int tid = threadIdx.x;
    int lane = tid & 31;
    for (int t = tid; t < 36864; t += 256) {
        int f = t / 576, r = t - f*576;
        s_w[r*WPITCH + f] = wc[t];
    }
    for (int idx = tid; idx < HPOS*16; idx += 256) {
        int pos = idx >> 4, c4 = idx & 15;
        int hy = pos / (CTX+2), hx = pos - hy*(CTX+2);
        int gy = y0 + hy - 1, gx = x0 + hx - 1;
        float4 v = make_float4(0.f,0.f,0.f,0.f);
        if (gy >= 0 && gy < 512 && gx >= 0 && gx < 48)
            v = *(const float4*)&d_dense[(((size_t)bb*512 + gy)*48 + gx)*64 + c4*4];
        float* s = &s_in[pos*IPITCH + c4*4];
        s[0]=v.x; s[1]=v.y; s[2]=v.z; s[3]=v.w;
    }
    if (tid < 128) sstat[tid] = 0.f;
    __syncthreads();
    int fs = tid >> 5;
    int ps = tid & 31;
    int lyg = ps >> 4;
    int lx  = ps & 15;
    ull acc[4][4];
    #pragma unroll
    for (int r = 0; r < 4; r++)
        #pragma unroll
        for (int j = 0; j < 4; j++) acc[r][j] = 0ULL;
    for (int cin = 0; cin < 64; cin++) {
        ull pin[6][3];
        #pragma unroll
        for (int rr = 0; rr < 6; rr++)
            #pragma unroll
            for (int cc = 0; cc < 3; cc++)
                pin[rr][cc] = pk2(s_in[((lyg*4+rr)*(CTX+2) + lx + cc)*IPITCH + cin]);
        #pragma unroll
        for (int tap = 0; tap < 9; tap++) {
            int dy = tap/3, dx = tap - dy*3;
            const ulonglong2* wp = (const ulonglong2*)&s_w[(cin*9+tap)*WPITCH + fs*8];
            ulonglong2 w0 = wp[0], w1 = wp[1];
            #pragma unroll
            for (int r = 0; r < 4; r++) {
                ull v = pin[r+dy][dx];
                ffma2(acc[r][0], v, w0.x); ffma2(acc[r][1], v, w0.y);
                ffma2(acc[r][2], v, w1.x); ffma2(acc[r][3], v, w1.y);
            }
        }
    }
    int gx = x0 + lx;
    #pragma unroll
    for (int r = 0; r < 4; r++) {
        int gy = y0 + lyg*4 + r;
        ulonglong2* o = (ulonglong2*)&d_conv[(((size_t)bb*512 + gy)*48 + gx)*64 + fs*8];
        o[0] = make_ulonglong2(acc[r][0], acc[r][1]);
        o[1] = make_ulonglong2(acc[r][2], acc[r][3]);
    }
    // fused stats
    #pragma unroll
    for (int j = 0; j < 4; j++) {
        ull s  = add2(add2(acc[0][j], acc[1][j]), add2(acc[2][j], acc[3][j]));
        ull s2 = add2(add2(sq2(acc[0][j]), sq2(acc[1][j])), add2(sq2(acc[2][j]), sq2(acc[3][j])));
        s = warp_red2(s); s2 = warp_red2(s2);
        if (lane == 0) {
            int ch = fs*8 + 2*j;
            float a, b;
            unpack2(s, a, b);
            atomicAdd(&sstat[ch], a); atomicAdd(&sstat[ch+1], b);
            unpack2(s2, a, b);
            atomicAdd(&sstat[64+ch], a); atomicAdd(&sstat[64+ch+1], b);
        }
    }
    __syncthreads();
    if (tid < 128) atomicAdd(&d_stats[384+tid], sstat[tid]);
    unsigned nblocks = gridDim.x * gridDim.y * gridDim.z;
    bn_finalize(2, nblocks, tid, 64, 1.0f/98304.0f, 384, 384, gc, bc);
}

// lin3: 128 -> 64, fused stats + finalize
__global__ void __launch_bounds__(256) k_lin3(const float* __restrict__ pts,
        const float* __restrict__ cylidx, const float* __restrict__ w3,
        const float* __restrict__ g3, const float* __restrict__ b3, int n, float invn) {
    __shared__ float sw3[128*68];
    __shared__ float pa[64], pc[64], ca[64], cs[64];
    __shared__ float sstat[128];
    int tid = threadIdx.x;
    for (int t = tid; t < 8192; t += 256) { int o = t >> 7, k = t & 127; sw3[k*68+o] = w3[t]; }
    if (tid < 64) {
        pa[tid] = d_bn[192+tid]; pc[tid] = d_bn[320+tid];
        ca[tid] = d_bn[384+tid]; cs[tid] = d_bn[448+tid];
    }
    if (tid < 128) sstat[tid] = 0.f;
    __syncthreads();
    int w = tid >> 5, lane = tid & 31;
    int hh = w & 1, g = w >> 1;
    int gp = blockIdx.x*128 + g*32 + lane;
    int p0 = 2*gp;
    bool vld = p0 < n;
    bool ok1 = (p0+1) < n;
    int p1 = ok1 ? p0+1 : p0;

    ull acc0[16], acc1[16];
    #pragma unroll
    for (int j = 0; j < 16; j++) { acc0[j]=0ULL; acc1[j]=0ULL; }

    if (vld) {
        const float4* q0 = (const float4*)&d_lin2[(size_t)p0*128 + 64];
        const float4* q1 = (const float4*)&d_lin2[(size_t)p1*128 + 64];
        #pragma unroll 2
        for (int kk = 0; kk < 16; kk++) {
            float4 a = q0[kk], b = q1[kk];
            int kb = kk*4;
            float av[4] = {a.x,a.y,a.z,a.w};
            float bv[4] = {b.x,b.y,b.z,b.w};
            #pragma unroll
            for (int j = 0; j < 4; j++) {
                int c = kb + j;
                ull v0 = pk2(fmaxf(fmaf(av[j], pa[c], pc[c]), 0.f));
                ull v1 = pk2(fmaxf(fmaf(bv[j], pa[c], pc[c]), 0.f));
                const ulonglong2* wp = (const ulonglong2*)&sw3[c*68 + hh*32];
                #pragma unroll
                for (int m = 0; m < 8; m++) {
                    ulonglong2 wv = wp[m];
                    ffma2(acc0[2*m],   v0, wv.x); ffma2(acc0[2*m+1], v0, wv.y);
                    ffma2(acc1[2*m],   v1, wv.x); ffma2(acc1[2*m+1], v1, wv.y);
                }
            }
        }
        float wA[2], wB[2], wC[2], wD[2];
        long offA[2], offB[2], offC[2], offD[2];
        int pp[2] = {p0, p1};
        #pragma unroll
        for (int s = 0; s < 2; s++) {
            int i = pp[s];
            float yq = cylidx[2*(size_t)i], xq = cylidx[2*(size_t)i+1];
            int y0i = (int)floorf(yq); int y1i = min(y0i+1, 511); y0i = min(max(y0i,0), 511);
            int x0i = (int)floorf(xq); int x1i = min(x0i+1, 47);  x0i = min(max(x0i,0), 47);
            wA[s] = ((float)x1i - xq)*((float)y1i - yq);
            wB[s] = ((float)x1i - xq)*(yq - (float)y0i);
            wC[s] = (xq - (float)x0i)*((float)y1i - yq);
            wD[s] = (xq - (float)x0i)*(yq - (float)y0i);
            int b = (int)pts[(size_t)i*5];
            long base = (long)b*512*48*64;
            offA[s] = base + ((long)y0i*48 + x0i)*64;
            offB[s] = base + ((long)y1i*48 + x0i)*64;
            offC[s] = base + ((long)y0i*48 + x1i)*64;
            offD[s] = base + ((long)y1i*48 + x1i)*64;
        }
        #pragma unroll 2
        for (int kk = 0; kk < 16; kk++) {
            float4 A0 = *(const float4*)&d_conv[offA[0] + kk*4];
            float4 B0 = *(const float4*)&d_conv[offB[0] + kk*4];
            float4 C0 = *(const float4*)&d_conv[offC[0] + kk*4];
            float4 D0 = *(const float4*)&d_conv[offD[0] + kk*4];
            float4 A1 = *(const float4*)&d_conv[offA[1] + kk*4];
            float4 B1 = *(const float4*)&d_conv[offB[1] + kk*4];
            float4 C1 = *(const float4*)&d_conv[offC[1] + kk*4];
            float4 D1 = *(const float4*)&d_conv[offD[1] + kk*4];
            float a0v[4] = {A0.x,A0.y,A0.z,A0.w}, b0v[4] = {B0.x,B0.y,B0.z,B0.w};
            float c0v[4] = {C0.x,C0.y,C0.z,C0.w}, d0v[4] = {D0.x,D0.y,D0.z,D0.w};
            float a1v[4] = {A1.x,A1.y,A1.z,A1.w}, b1v[4] = {B1.x,B1.y,B1.z,B1.w};
            float c1v[4] = {C1.x,C1.y,C1.z,C1.w}, d1v[4] = {D1.x,D1.y,D1.z,D1.w};
            int kb = kk*4;
            #pragma unroll
            for (int j = 0; j < 4; j++) {
                int c = kb + j;
                float f0 = wA[0]*fmaxf(fmaf(a0v[j], ca[c], cs[c]), 0.f)
                         + wB[0]*fmaxf(fmaf(b0v[j], ca[c], cs[c]), 0.f)
                         + wC[0]*fmaxf(fmaf(c0v[j], ca[c], cs[c]), 0.f)
                         + wD[0]*fmaxf(fmaf(d0v[j], ca[c], cs[c]), 0.f);
                float f1 = wA[1]*fmaxf(fmaf(a1v[j], ca[c], cs[c]), 0.f)
                         + wB[1]*fmaxf(fmaf(b1v[j], ca[c], cs[c]), 0.f)
                         + wC[1]*fmaxf(fmaf(c1v[j], ca[c], cs[c]), 0.f)
                         + wD[1]*fmaxf(fmaf(d1v[j], ca[c], cs[c]), 0.f);
                ull v0 = pk2(f0), v1 = pk2(f1);
                const ulonglong2* wp = (const ulonglong2*)&sw3[(64+c)*68 + hh*32];
                #pragma unroll
                for (int m = 0; m < 8; m++) {
                    ulonglong2 wv = wp[m];
                    ffma2(acc0[2*m],   v0, wv.x); ffma2(acc0[2*m+1], v0, wv.y);
                    ffma2(acc1[2*m],   v1, wv.x); ffma2(acc1[2*m+1], v1, wv.y);
                }
            }
        }
        ulonglong2* o0 = (ulonglong2*)&d_lin1[(size_t)p0*64 + hh*32];
        #pragma unroll
        for (int m = 0; m < 8; m++) o0[m] = make_ulonglong2(acc0[2*m], acc0[2*m+1]);
        if (ok1) {
            ulonglong2* o1 = (ulonglong2*)&d_lin1[(size_t)p1*64 + hh*32];
            #pragma unroll
            for (int m = 0; m < 8; m++) o1[m] = make_ulonglong2(acc1[2*m], acc1[2*m+1]);
        }
    }
    #pragma unroll
    for (int m = 0; m < 16; m++) {
        ull s = 0ULL, s2 = 0ULL;
        if (vld) {
            s = acc0[m]; s2 = sq2(acc0[m]);
            if (ok1) { s = add2(s, acc1[m]); s2 = add2(s2, sq2(acc1[m])); }
        }
        s = warp_red2(s); s2 = warp_red2(s2);
        if (lane == 0) {
            int ch = hh*32 + 2*m;
            float a, b;
            unpack2(s, a, b);
            atomicAdd(&sstat[ch], a); atomicAdd(&sstat[ch+1], b);
            unpack2(s2, a, b);
            atomicAdd(&sstat[64+ch], a); atomicAdd(&sstat[64+ch+1], b);
        }
    }
    __syncthreads();
    if (tid < 128) atomicAdd(&d_stats[512+tid], sstat[tid]);
    bn_finalize(3, gridDim.x, tid, 64, invn, 512, 512, g3, b3);
}

// final: bn_relu(lin3) -> out; atomicMax into bev_max; extra blocks do voxel coords
__global__ void k_final(const int* __restrict__ binv, const int* __restrict__ bcoord,
                        float* __restrict__ out, int n, int nb, int nblk) {
    if (blockIdx.x >= nblk) {
        int i = (blockIdx.x - nblk)*blockDim.x + threadIdx.x;
        if (i < nb) {
            int c = bcoord[i];
            int vb = c / 55000;
            int r  = c % 55000;
            int vx = r / 250;
            int vy = r % 250;
            float* o = out + (size_t)n*64 + (size_t)nb*64 + (size_t)i*4;
            o[0] = (float)vb; o[1] = 0.f; o[2] = (float)vy; o[3] = (float)vx;
        }
        return;
    }
    __shared__ float sa[64], sc[64];
    if (threadIdx.x < 64) { sa[threadIdx.x] = d_bn[512+threadIdx.x]; sc[threadIdx.x] = d_bn[576+threadIdx.x]; }
    __syncthreads();
    int i = blockIdx.x*blockDim.x + threadIdx.x;
    if (i >= n) return;
    int bi = binv[i];
    const float4* src = (const float4*)&d_lin1[(size_t)i*64];
    float4* dst = (float4*)(out + (size_t)i*64);
    unsigned* mx = (unsigned*)(out + (size_t)n*64 + (size_t)bi*64);
    #pragma unroll
    for (int j = 0; j < 16; j++) {
        float4 v = src[j];
        int c = j*4;
        float r0 = fmaxf(fmaf(v.x, sa[c+0], sc[c+0]), 0.f);
        float r1 = fmaxf(fmaf(v.y, sa[c+1], sc[c+1]), 0.f);
        float r2 = fmaxf(fmaf(v.z, sa[c+2], sc[c+2]), 0.f);
        float r3 = fmaxf(fmaf(v.w, sa[c+3], sc[c+3]), 0.f);
        dst[j] = make_float4(r0, r1, r2, r3);
        atomicMax(mx+c+0, __float_as_uint(r0));
        atomicMax(mx+c+1, __float_as_uint(r1));
        atomicMax(mx+c+2, __float_as_uint(r2));
        atomicMax(mx+c+3, __float_as_uint(r3));
    }
}

// ---------------- launcher ----------------
extern "C" void kernel_launch(void* const* d_in, const int* in_sizes, int n_in,
                              void* d_out, int out_size) {
    const float* points = (const float*)d_in[0];
    const float* pcyl   = (const float*)d_in[1];
    const float* cylidx = (const float*)d_in[2];
    const float* bevidx = (const float*)d_in[3];
    const float* w1 = (const float*)d_in[4];
    const float* g1 = (const float*)d_in[5];
    const float* b1 = (const float*)d_in[6];
    const float* w2 = (const float*)d_in[7];
    const float* g2 = (const float*)d_in[8];
    const float* b2 = (const float*)d_in[9];
    const float* wc = (const float*)d_in[10];
    const float* gc = (const float*)d_in[11];
    const float* bc = (const float*)d_in[12];
    const float* w3 = (const float*)d_in[13];
    const float* g3 = (const float*)d_in[14];
    const float* b3 = (const float*)d_in[15];
    const int* binv   = (const int*)d_in[16];
    const int* bcoord = (const int*)d_in[17];
    const int* cinv   = (const int*)d_in[18];

    int n  = in_sizes[0] / 5;
    int nb = in_sizes[17];
    int nc = in_sizes[19];
    float* out = (float*)d_out;
    float invn = 1.0f/(float)n;

    static bool attr_done = false;
    if (!attr_done) {
        cudaFuncSetAttribute(k_conv, cudaFuncAttributeMaxDynamicSharedMemorySize, CONV_SMEM);
        attr_done = true;
    }

    int nblk = (n + 255) / 256;
    k_zero<<<512, 256>>>(out + (size_t)n*64, nb, nc);
    k_scatter<<<nblk, 256>>>(points, pcyl, binv, cinv, n);
    k_lin1<<<nblk, 256>>>(points, pcyl, cylidx, bevidx, binv, cinv, w1, g1, b1, n, invn);
    k_lin2<<<(n + 127)/128, 256>>>(w2, g2, b2, n, invn);
    k_cylmax<<<nblk, 256>>>(points, cylidx, n);
    dim3 cg(3, 64, 4);
    k_conv<<<cg, 256, CONV_SMEM>>>(wc, gc, bc);
    k_lin3<<<(n + 255)/256, 256>>>(points, cylidx, w3, g3, b3, n, invn);
    int vblk = (nb + 255) / 256;
    k_final<<<nblk + vblk, 256>>>(binv, bcoord, out, n, nb, nblk);
}

// round 5
// speedup vs baseline: 1.0276x; 1.0276x over previous
#include <cuda_runtime.h>
#include <math.h>

typedef unsigned long long ull;

// ---------------- problem constants ----------------
#define NPTS_MAX 200000
#define NB_MAX   220000
#define NC_MAX   98304
#define IMG_ELEMS (4*512*48*64)

#define CVS0 (6.2831853f/512.0f)
#define CVS1 0.125f
#define CR0  (-3.14159265f)
#define CR1  (-2.0f)

// ---------------- scratch ----------------
__device__ float d_lin1[(size_t)NPTS_MAX*64];
__device__ float d_lin2[(size_t)NPTS_MAX*128];
__device__ float d_gath[(size_t)NPTS_MAX*64];
__device__ float d_lin3[(size_t)NPTS_MAX*64];
__device__ float d_dense[IMG_ELEMS];
__device__ float d_conv[IMG_ELEMS];
__device__ float d_bevsum[NB_MAX*4];
__device__ float d_cylsum[NC_MAX*4];
__device__ float d_stats[1024];   // lin1@0, lin2@128, conv@384, lin3@512
__device__ float d_bn[1024];      // lin1 a@0 c@64; lin2 a@128 c@256; conv a@384 c@448; lin3 a@512 c@576

// ---------------- f32x2 helpers ----------------
__device__ __forceinline__ ull pk2(float v) {
    ull r; unsigned u = __float_as_uint(v);
    asm("mov.b64 %0, {%1, %1};" : "=l"(r) : "r"(u));
    return r;
}
__device__ __forceinline__ void ffma2(ull& d, ull a, ull b) {
    asm("fma.rn.f32x2 %0, %1, %2, %0;" : "+l"(d) : "l"(a), "l"(b));
}
__device__ __forceinline__ void unpack2(ull v, float& lo, float& hi) {
    asm("mov.b64 {%0, %1}, %2;" : "=f"(lo), "=f"(hi) : "l"(v));
}

// ---------------- kernels ----------------
__global__ void __launch_bounds__(256) k_zero(float* outbev, int nb, int nc) {
    size_t tid = (size_t)blockIdx.x * blockDim.x + threadIdx.x;
    size_t stride = (size_t)gridDim.x * blockDim.x;
    float4 z = make_float4(0.f, 0.f, 0.f, 0.f);
    float4* p = (float4*)d_dense;
    for (size_t i = tid; i < IMG_ELEMS/4; i += stride) p[i] = z;
    float4* q = (float4*)outbev;
    size_t obw = (size_t)nb * 16;
    for (size_t i = tid; i < obw; i += stride) q[i] = z;
    float4* bs = (float4*)d_bevsum;
    for (size_t i = tid; i < (size_t)nb; i += stride) bs[i] = z;
    float4* cs = (float4*)d_cylsum;
    for (size_t i = tid; i < (size_t)nc; i += stride) cs[i] = z;
    if (tid < 256) ((float4*)d_stats)[tid] = z;
}

__global__ void k_scatter(const float* __restrict__ pts, const float* __restrict__ pcyl,
                          const int* __restrict__ binv, const int* __restrict__ cinv, int n) {
    int i = blockIdx.x*blockDim.x + threadIdx.x;
    if (i >= n) return;
    float x = pts[(size_t)i*5+1], y = pts[(size_t)i*5+2], z = pts[(size_t)i*5+3];
    int bi = binv[i], ci = cinv[i];
    atomicAdd(&d_bevsum[bi*4+0], x);
    atomicAdd(&d_bevsum[bi*4+1], y);
    atomicAdd(&d_bevsum[bi*4+2], z);
    atomicAdd(&d_bevsum[bi*4+3], 1.0f);
    float p0 = pcyl[(size_t)i*3], p1 = pcyl[(size_t)i*3+1], p2 = pcyl[(size_t)i*3+2];
    atomicAdd(&d_cylsum[ci*4+0], p0);
    atomicAdd(&d_cylsum[ci*4+1], p1);
    atomicAdd(&d_cylsum[ci*4+2], p2);
    atomicAdd(&d_cylsum[ci*4+3], 1.0f);
}

__global__ void __launch_bounds__(256) k_lin1(
        const float* __restrict__ pts, const float* __restrict__ pcyl,
        const float* __restrict__ cylidx, const float* __restrict__ bevidx,
        const int* __restrict__ binv, const int* __restrict__ cinv,
        const float* __restrict__ w1, int n) {
    __shared__ float sw[16*64];
    for (int t = threadIdx.x; t < 1024; t += 256) { int o = t >> 4, k = t & 15; sw[k*64+o] = w1[t]; }
    __syncthreads();
    int i = blockIdx.x*256 + threadIdx.x;
    if (i >= n) return;
    float x = pts[(size_t)i*5+1], y = pts[(size_t)i*5+2], z = pts[(size_t)i*5+3], it = pts[(size_t)i*5+4];
    float phi = pcyl[(size_t)i*3], zc = pcyl[(size_t)i*3+1], rho = pcyl[(size_t)i*3+2];
    float bix = bevidx[2*(size_t)i], biy = bevidx[2*(size_t)i+1];
    float cix = cylidx[2*(size_t)i], ciy = cylidx[2*(size_t)i+1];
    int bi = binv[i], ci = cinv[i];
    float bcnt = d_bevsum[bi*4+3];
    float bmx = d_bevsum[bi*4]/bcnt, bmy = d_bevsum[bi*4+1]/bcnt;
    float ccnt = d_cylsum[ci*4+3];
    float cm0 = d_cylsum[ci*4]/ccnt, cm1 = d_cylsum[ci*4+1]/ccnt;
    float f[16];
    f[0]=x; f[1]=y; f[2]=z; f[3]=phi; f[4]=zc; f[5]=rho;
    f[6] = x - ((floorf(bix)+0.5f)*0.32f + 0.0f);
    f[7] = y - ((floorf(biy)+0.5f)*0.32f + (-40.0f));
    f[8] = phi - ((floorf(cix)+0.5f)*CVS0 + CR0);
    f[9] = zc  - ((floorf(ciy)+0.5f)*CVS1 + CR1);
    f[10]= x - bmx; f[11]= y - bmy;
    f[12]= phi - cm0; f[13]= zc - cm1;
    f[14]= sqrtf(x*x + y*y + z*z);
    f[15]= it;
    ull acc[32];
    #pragma unroll
    for (int o = 0; o < 32; o++) acc[o] = 0ULL;
    #pragma unroll
    for (int k = 0; k < 16; k++) {
        ull v = pk2(f[k]);
        const ulonglong2* wr = (const ulonglong2*)&sw[k*64];
        #pragma unroll
        for (int m = 0; m < 16; m++) {
            ulonglong2 w = wr[m];
            ffma2(acc[2*m], v, w.x); ffma2(acc[2*m+1], v, w.y);
        }
    }
    ulonglong2* op = (ulonglong2*)&d_lin1[(size_t)i*64];
    #pragma unroll
    for (int m = 0; m < 16; m++) op[m] = make_ulonglong2(acc[2*m], acc[2*m+1]);
}

// per-channel sum/sumsq over [rows x C]
__global__ void k_stats(const float* __restrict__ data, int rows, int C, int shift, float* __restrict__ out) {
    int tid = threadIdx.x;
    int c = tid & (C-1);
    int sub = tid >> shift;
    int rpb = 256 >> shift;
    float s = 0.f, s2 = 0.f;
    for (long r = (long)blockIdx.x*rpb + sub; r < rows; r += (long)gridDim.x*rpb) {
        float v = data[(size_t)r*C + c];
        s += v; s2 += v*v;
    }
    __shared__ float sh[512];
    sh[tid] = s; sh[256+tid] = s2;
    __syncthreads();
    if (sub == 0) {
        for (int j = 1; j < rpb; j++) { s += sh[j*C + c]; s2 += sh[256 + j*C + c]; }
        atomicAdd(&out[c], s);
        atomicAdd(&out[C+c], s2);
    }
}

__global__ void k_finalize(const float* __restrict__ g, const float* __restrict__ b,
                           int C, float invn, int sbase, int bbase) {
    int c = threadIdx.x;
    if (c < C) {
        float m = d_stats[sbase+c]*invn;
        float v = d_stats[sbase+C+c]*invn - m*m;
        float a = g[c]*rsqrtf(v + 1e-3f);
        d_bn[bbase+c]   = a;
        d_bn[bbase+C+c] = b[c] - m*a;
    }
}

// ---------------- lin2 GEMM: [N,64] @ [64,128]  (tile 128 pts x 64 outs per block) ----------------
// grid (ceil(n/128), 2), block 256, dyn smem
#define L2_SMEM ((64*132 + 64*68 + 128)*4)
__global__ void __launch_bounds__(256, 3) k_lin2(const float* __restrict__ w2, int n) {
    extern __shared__ float dsm[];
    float* s_act = dsm;               // [k][p] 64 x 132
    float* s_w   = dsm + 64*132;      // [k][o] 64 x 68
    float* sa    = dsm + 64*132 + 64*68;
    float* sc    = sa + 64;
    int tid = threadIdx.x;
    int oh = blockIdx.y;
    if (tid < 64) { sa[tid] = d_bn[tid]; sc[tid] = d_bn[64+tid]; }
    for (int t = tid; t < 4096; t += 256) {
        int o = t >> 6, k = t & 63;
        s_w[k*68 + o] = w2[((size_t)(oh*64 + o))*64 + k];
    }
    __syncthreads();
    int pbase = blockIdx.x*128;
    for (int idx = tid; idx < 128*16; idx += 256) {
        int lp = idx >> 4, kq = idx & 15;
        int p = pbase + lp;
        float4 v = make_float4(0.f,0.f,0.f,0.f);
        if (p < n) v = *(const float4*)&d_lin1[(size_t)p*64 + kq*4];
        int k = kq*4;
        s_act[(k+0)*132+lp] = fmaxf(fmaf(v.x, sa[k+0], sc[k+0]), 0.f);
        s_act[(k+1)*132+lp] = fmaxf(fmaf(v.y, sa[k+1], sc[k+1]), 0.f);
        s_act[(k+2)*132+lp] = fmaxf(fmaf(v.z, sa[k+2], sc[k+2]), 0.f);
        s_act[(k+3)*132+lp] = fmaxf(fmaf(v.w, sa[k+3], sc[k+3]), 0.f);
    }
    __syncthreads();
    int tp = tid & 15, to = tid >> 4;
    int pb = tp*8, ob = to*4;
    ull acc[16];
    #pragma unroll
    for (int j = 0; j < 16; j++) acc[j] = 0ULL;
    #pragma unroll 4
    for (int k = 0; k < 64; k++) {
        ulonglong2 a01 = *(const ulonglong2*)&s_act[k*132 + pb];
        ulonglong2 a23 = *(const ulonglong2*)&s_act[k*132 + pb + 4];
        float4 w4 = *(const float4*)&s_w[k*68 + ob];
        ull w0 = pk2(w4.x), w1 = pk2(w4.y), w2p = pk2(w4.z), w3p = pk2(w4.w);
        ffma2(acc[0],  a01.x, w0);  ffma2(acc[1],  a01.y, w0);
        ffma2(acc[2],  a23.x, w0);  ffma2(acc[3],  a23.y, w0);
        ffma2(acc[4],  a01.x, w1);  ffma2(acc[5],  a01.y, w1);
        ffma2(acc[6],  a23.x, w1);  ffma2(acc[7],  a23.y, w1);
        ffma2(acc[8],  a01.x, w2p); ffma2(acc[9],  a01.y, w2p);
        ffma2(acc[10], a23.x, w2p); ffma2(acc[11], a23.y, w2p);
        ffma2(acc[12], a01.x, w3p); ffma2(acc[13], a01.y, w3p);
        ffma2(acc[14], a23.x, w3p); ffma2(acc[15], a23.y, w3p);
    }
    #pragma unroll
    for (int p2 = 0; p2 < 4; p2++) {
        int p = pbase + pb + p2*2;
        if (p >= n) break;
        float lo0,hi0,lo1,hi1,lo2,hi2,lo3,hi3;
        unpack2(acc[p2],    lo0, hi0);
        unpack2(acc[4+p2],  lo1, hi1);
        unpack2(acc[8+p2],  lo2, hi2);
        unpack2(acc[12+p2], lo3, hi3);
        *(float4*)&d_lin2[(size_t)p*128 + oh*64 + ob] = make_float4(lo0,lo1,lo2,lo3);
        if (p+1 < n)
            *(float4*)&d_lin2[(size_t)(p+1)*128 + oh*64 + ob] = make_float4(hi0,hi1,hi2,hi3);
    }
}

// segment-max of bn_relu(lin2[:, :64]) into dense image
__global__ void k_cylmax(const float* __restrict__ pts, const float* __restrict__ cylidx, int n) {
    __shared__ float sa[64], sc[64];
    if (threadIdx.x < 64) { sa[threadIdx.x] = d_bn[128+threadIdx.x]; sc[threadIdx.x] = d_bn[256+threadIdx.x]; }
    __syncthreads();
    int i = blockIdx.x*blockDim.x + threadIdx.x;
    if (i >= n) return;
    int b = (int)pts[(size_t)i*5];
    int iy = (int)floorf(cylidx[2*(size_t)i]);   iy = max(0, min(iy, 511));
    int ix = (int)floorf(cylidx[2*(size_t)i+1]); ix = max(0, min(ix, 47));
    unsigned* dst = (unsigned*)&d_dense[(((size_t)b*512 + iy)*48 + ix)*64];
    const float4* src = (const float4*)&d_lin2[(size_t)i*128];
    #pragma unroll
    for (int j = 0; j < 16; j++) {
        float4 v = src[j];
        int c = j*4;
        float r0 = fmaxf(fmaf(v.x, sa[c+0], sc[c+0]), 0.f);
        float r1 = fmaxf(fmaf(v.y, sa[c+1], sc[c+1]), 0.f);
        float r2 = fmaxf(fmaf(v.z, sa[c+2], sc[c+2]), 0.f);
        float r3 = fmaxf(fmaf(v.w, sa[c+3], sc[c+3]), 0.f);
        atomicMax(dst+c+0, __float_as_uint(r0));
        atomicMax(dst+c+1, __float_as_uint(r1));
        atomicMax(dst+c+2, __float_as_uint(r2));
        atomicMax(dst+c+3, __float_as_uint(r3));
    }
}

// 3x3 SAME conv, 64->64: weights resident, 16x8 tile, f32x2
#define CTX 16
#define CTY 8
#define HPOS ((CTY+2)*(CTX+2))
#define WPITCH 68
#define IPITCH 65
#define CONV_SMEM ((576*WPITCH + HPOS*IPITCH)*4)
__global__ void __launch_bounds__(256) k_conv(const float* __restrict__ wc) {
    extern __shared__ float dsm[];
    float* s_w  = dsm;
    float* s_in = dsm + 576*WPITCH;
    int x0 = blockIdx.x*CTX, y0 = blockIdx.y*CTY, bb = blockIdx.z;
    int tid = threadIdx.x;
    for (int t = tid; t < 36864; t += 256) {
        int f = t / 576, r = t - f*576;
        s_w[r*WPITCH + f] = wc[t];
    }
    for (int idx = tid; idx < HPOS*16; idx += 256) {
        int pos = idx >> 4, c4 = idx & 15;
        int hy = pos / (CTX+2), hx = pos - hy*(CTX+2);
        int gy = y0 + hy - 1, gx = x0 + hx - 1;
        float4 v = make_float4(0.f,0.f,0.f,0.f);
        if (gy >= 0 && gy < 512 && gx >= 0 && gx < 48)
            v = *(const float4*)&d_dense[(((size_t)bb*512 + gy)*48 + gx)*64 + c4*4];
        float* s = &s_in[pos*IPITCH + c4*4];
        s[0]=v.x; s[1]=v.y; s[2]=v.z; s[3]=v.w;
    }
    __syncthreads();
    int fs = tid >> 5;
    int ps = tid & 31;
    int lyg = ps >> 4;
    int lx  = ps & 15;
    ull acc[4][4];
    #pragma unroll
    for (int r = 0; r < 4; r++)
        #pragma unroll
        for (int j = 0; j < 4; j++) acc[r][j] = 0ULL;
    for (int cin = 0; cin < 64; cin++) {
        ull pin[6][3];
        #pragma unroll
        for (int rr = 0; rr < 6; rr++)
            #pragma unroll
            for (int cc = 0; cc < 3; cc++)
                pin[rr][cc] = pk2(s_in[((lyg*4+rr)*(CTX+2) + lx + cc)*IPITCH + cin]);
        #pragma unroll
        for (int tap = 0; tap < 9; tap++) {
            int dy = tap/3, dx = tap - dy*3;
            const ulonglong2* wp = (const ulonglong2*)&s_w[(cin*9+tap)*WPITCH + fs*8];
            ulonglong2 w0 = wp[0], w1 = wp[1];
            #pragma unroll
            for (int r = 0; r < 4; r++) {
                ull v = pin[r+dy][dx];
                ffma2(acc[r][0], v, w0.x); ffma2(acc[r][1], v, w0.y);
                ffma2(acc[r][2], v, w1.x); ffma2(acc[r][3], v, w1.y);
            }
        }
    }
    int gx = x0 + lx;
    #pragma unroll
    for (int r = 0; r < 4; r++) {
        int gy = y0 + lyg*4 + r;
        ulonglong2* o = (ulonglong2*)&d_conv[(((size_t)bb*512 + gy)*48 + gx)*64 + fs*8];
        o[0] = make_ulonglong2(acc[r][0], acc[r][1]);
        o[1] = make_ulonglong2(acc[r][2], acc[r][3]);
    }
}

// gather: bilinear of bn_relu(conv) per point -> d_gath[N][64]
__global__ void __launch_bounds__(256) k_gather(const float* __restrict__ pts,
        const float* __restrict__ cylidx, int n) {
    __shared__ float ca[64], cs[64];
    if (threadIdx.x < 64) { ca[threadIdx.x] = d_bn[384+threadIdx.x]; cs[threadIdx.x] = d_bn[448+threadIdx.x]; }
    __syncthreads();
    int i = blockIdx.x*256 + threadIdx.x;
    if (i >= n) return;
    float yq = cylidx[2*(size_t)i], xq = cylidx[2*(size_t)i+1];
    int y0i = (int)floorf(yq); int y1i = min(y0i+1, 511); y0i = min(max(y0i,0), 511);
    int x0i = (int)floorf(xq); int x1i = min(x0i+1, 47);  x0i = min(max(x0i,0), 47);
    float wa = ((float)x1i - xq)*((float)y1i - yq);
    float wb = ((float)x1i - xq)*(yq - (float)y0i);
    float wcw= (xq - (float)x0i)*((float)y1i - yq);
    float wd = (xq - (float)x0i)*(yq - (float)y0i);
    int b = (int)pts[(size_t)i*5];
    size_t base = (size_t)b*512*48*64;
    const float4* A = (const float4*)&d_conv[base + ((size_t)y0i*48 + x0i)*64];
    const float4* Bp= (const float4*)&d_conv[base + ((size_t)y1i*48 + x0i)*64];
    const float4* Cp= (const float4*)&d_conv[base + ((size_t)y0i*48 + x1i)*64];
    const float4* Dp= (const float4*)&d_conv[base + ((size_t)y1i*48 + x1i)*64];
    float4* out = (float4*)&d_gath[(size_t)i*64];
    #pragma unroll 4
    for (int kk = 0; kk < 16; kk++) {
        float4 av = A[kk], bv = Bp[kk], cv = Cp[kk], dv = Dp[kk];
        int c = kk*4;
        float4 r;
        r.x = wa*fmaxf(fmaf(av.x, ca[c+0], cs[c+0]),0.f) + wb*fmaxf(fmaf(bv.x, ca[c+0], cs[c+0]),0.f)
            + wcw*fmaxf(fmaf(cv.x, ca[c+0], cs[c+0]),0.f) + wd*fmaxf(fmaf(dv.x, ca[c+0], cs[c+0]),0.f);
        r.y = wa*fmaxf(fmaf(av.y, ca[c+1], cs[c+1]),0.f) + wb*fmaxf(fmaf(bv.y, ca[c+1], cs[c+1]),0.f)
            + wcw*fmaxf(fmaf(cv.y, ca[c+1], cs[c+1]),0.f) + wd*fmaxf(fmaf(dv.y, ca[c+1], cs[c+1]),0.f);
        r.z = wa*fmaxf(fmaf(av.z, ca[c+2], cs[c+2]),0.f) + wb*fmaxf(fmaf(bv.z, ca[c+2], cs[c+2]),0.f)
            + wcw*fmaxf(fmaf(cv.z, ca[c+2], cs[c+2]),0.f) + wd*fmaxf(fmaf(dv.z, ca[c+2], cs[c+2]),0.f);
        r.w = wa*fmaxf(fmaf(av.w, ca[c+3], cs[c+3]),0.f) + wb*fmaxf(fmaf(bv.w, ca[c+3], cs[c+3]),0.f)
            + wcw*fmaxf(fmaf(cv.w, ca[c+3], cs[c+3]),0.f) + wd*fmaxf(fmaf(dv.w, ca[c+3], cs[c+3]),0.f);
        out[kk] = r;
    }
}

// ---------------- lin3 GEMM: [N,128] @ [128,64]  (tile 128 pts x 64 outs) ----------------
#define L3_SMEM ((128*132 + 128*68 + 128)*4)
__global__ void __launch_bounds__(256, 2) k_lin3(const float* __restrict__ w3, int n) {
    extern __shared__ float dsm[];
    float* s_act = dsm;                 // [k][p] 128 x 132
    float* s_w   = dsm + 128*132;       // [k][o] 128 x 68
    float* pa    = dsm + 128*132 + 128*68;
    float* pc    = pa + 64;
    int tid = threadIdx.x;
    if (tid < 64) { pa[tid] = d_bn[192+tid]; pc[tid] = d_bn[320+tid]; }
    for (int t = tid; t < 8192; t += 256) {
        int o = t >> 7, k = t & 127;
        s_w[k*68 + o] = w3[(size_t)o*128 + k];
    }
    __syncthreads();
    int pbase = blockIdx.x*128;
    for (int idx = tid; idx < 128*32; idx += 256) {
        int lp = idx >> 5, kq = idx & 31;
        int p = pbase + lp;
        int k = kq*4;
        float4 v = make_float4(0.f,0.f,0.f,0.f);
        if (p < n) {
            if (kq < 16) {
                v = *(const float4*)&d_lin2[(size_t)p*128 + 64 + kq*4];
                v.x = fmaxf(fmaf(v.x, pa[k+0], pc[k+0]), 0.f);
                v.y = fmaxf(fmaf(v.y, pa[k+1], pc[k+1]), 0.f);
                v.z = fmaxf(fmaf(v.z, pa[k+2], pc[k+2]), 0.f);
                v.w = fmaxf(fmaf(v.w, pa[k+3], pc[k+3]), 0.f);
            } else {
                v = *(const float4*)&d_gath[(size_t)p*64 + (kq-16)*4];
            }
        }
        s_act[(k+0)*132+lp] = v.x;
        s_act[(k+1)*132+lp] = v.y;
        s_act[(k+2)*132+lp] = v.z;
        s_act[(k+3)*132+lp] = v.w;
    }
    __syncthreads();
    int tp = tid & 15, to = tid >> 4;
    int pb = tp*8, ob = to*4;
    ull acc[16];
    #pragma unroll
    for (int j = 0; j < 16; j++) acc[j] = 0ULL;
    #pragma unroll 4
    for (int k = 0; k < 128; k++) {
        ulonglong2 a01 = *(const ulonglong2*)&s_act[k*132 + pb];
        ulonglong2 a23 = *(const ulonglong2*)&s_act[k*132 + pb + 4];
        float4 w4 = *(const float4*)&s_w[k*68 + ob];
        ull w0 = pk2(w4.x), w1 = pk2(w4.y), w2p = pk2(w4.z), w3p = pk2(w4.w);
        ffma2(acc[0],  a01.x, w0);  ffma2(acc[1],  a01.y, w0);
        ffma2(acc[2],  a23.x, w0);  ffma2(acc[3],  a23.y, w0);
        ffma2(acc[4],  a01.x, w1);  ffma2(acc[5],  a01.y, w1);
        ffma2(acc[6],  a23.x, w1);  ffma2(acc[7],  a23.y, w1);
        ffma2(acc[8],  a01.x, w2p); ffma2(acc[9],  a01.y, w2p);
        ffma2(acc[10], a23.x, w2p); ffma2(acc[11], a23.y, w2p);
        ffma2(acc[12], a01.x, w3p); ffma2(acc[13], a01.y, w3p);
        ffma2(acc[14], a23.x, w3p); ffma2(acc[15], a23.y, w3p);
    }
    #pragma unroll
    for (int p2 = 0; p2 < 4; p2++) {
        int p = pbase + pb + p2*2;
        if (p >= n) break;
        float lo0,hi0,lo1,hi1,lo2,hi2,lo3,hi3;
        unpack2(acc[p2],    lo0, hi0);
        unpack2(acc[4+p2],  lo1, hi1);
        unpack2(acc[8+p2],  lo2, hi2);
        unpack2(acc[12+p2], lo3, hi3);
        *(float4*)&d_lin3[(size_t)p*64 + ob] = make_float4(lo0,lo1,lo2,lo3);
        if (p+1 < n)
            *(float4*)&d_lin3[(size_t)(p+1)*64 + ob] = make_float4(hi0,hi1,hi2,hi3);
    }
}

// final: bn_relu(lin3) -> out; atomicMax into bev_max; extra blocks do voxel coords
__global__ void k_final(const int* __restrict__ binv, const int* __restrict__ bcoord,
                        float* __restrict__ out, int n, int nb, int nblk) {
    if (blockIdx.x >= nblk) {
        int i = (blockIdx.x - nblk)*blockDim.x + threadIdx.x;
        if (i < nb) {
            int c = bcoord[i];
            int vb = c / 55000;
            int r  = c % 55000;
            int vx = r / 250;
            int vy = r % 250;
            float* o = out + (size_t)n*64 + (size_t)nb*64 + (size_t)i*4;
            o[0] = (float)vb; o[1] = 0.f; o[2] = (float)vy; o[3] = (float)vx;
        }
        return;
    }
    __shared__ float sa[64], sc[64];
    if (threadIdx.x < 64) { sa[threadIdx.x] = d_bn[512+threadIdx.x]; sc[threadIdx.x] = d_bn[576+threadIdx.x]; }
    __syncthreads();
    int i = blockIdx.x*blockDim.x + threadIdx.x;
    if (i >= n) return;
    int bi = binv[i];
    const float4* src = (const float4*)&d_lin3[(size_t)i*64];
    float4* dst = (float4*)(out + (size_t)i*64);
    unsigned* mx = (unsigned*)(out + (size_t)n*64 + (size_t)bi*64);
    #pragma unroll
    for (int j = 0; j < 16; j++) {
        float4 v = src[j];
        int c = j*4;
        float r0 = fmaxf(fmaf(v.x, sa[c+0], sc[c+0]), 0.f);
        float r1 = fmaxf(fmaf(v.y, sa[c+1], sc[c+1]), 0.f);
        float r2 = fmaxf(fmaf(v.z, sa[c+2], sc[c+2]), 0.f);
        float r3 = fmaxf(fmaf(v.w, sa[c+3], sc[c+3]), 0.f);
        dst[j] = make_float4(r0, r1, r2, r3);
        atomicMax(mx+c+0, __float_as_uint(r0));
        atomicMax(mx+c+1, __float_as_uint(r1));
        atomicMax(mx+c+2, __float_as_uint(r2));
        atomicMax(mx+c+3, __float_as_uint(r3));
    }
}

// ---------------- launcher ----------------
extern "C" void kernel_launch(void* const* d_in, const int* in_sizes, int n_in,
                              void* d_out, int out_size) {
    const float* points = (const float*)d_in[0];
    const float* pcyl   = (const float*)d_in[1];
    const float* cylidx = (const float*)d_in[2];
    const float* bevidx = (const float*)d_in[3];
    const float* w1 = (const float*)d_in[4];
    const float* g1 = (const float*)d_in[5];
    const float* b1 = (const float*)d_in[6];
    const float* w2 = (const float*)d_in[7];
    const float* g2 = (const float*)d_in[8];
    const float* b2 = (const float*)d_in[9];
    const float* wc = (const float*)d_in[10];
    const float* gc = (const float*)d_in[11];
    const float* bc = (const float*)d_in[12];
    const float* w3 = (const float*)d_in[13];
    const float* g3 = (const float*)d_in[14];
    const float* b3 = (const float*)d_in[15];
    const int* binv   = (const int*)d_in[16];
    const int* bcoord = (const int*)d_in[17];
    const int* cinv   = (const int*)d_in[18];

    int n  = in_sizes[0] / 5;
    int nb = in_sizes[17];
    int nc = in_sizes[19];
    float* out = (float*)d_out;
    float invn = 1.0f/(float)n;

    void *p_lin1, *p_lin2, *p_conv, *p_lin3, *p_stats;
    cudaGetSymbolAddress(&p_lin1, d_lin1);
    cudaGetSymbolAddress(&p_lin2, d_lin2);
    cudaGetSymbolAddress(&p_conv, d_conv);
    cudaGetSymbolAddress(&p_lin3, d_lin3);
    cudaGetSymbolAddress(&p_stats, d_stats);

    static bool attr_done = false;
    if (!attr_done) {
        cudaFuncSetAttribute(k_conv, cudaFuncAttributeMaxDynamicSharedMemorySize, CONV_SMEM);
        cudaFuncSetAttribute(k_lin2, cudaFuncAttributeMaxDynamicSharedMemorySize, L2_SMEM);
        cudaFuncSetAttribute(k_lin3, cudaFuncAttributeMaxDynamicSharedMemorySize, L3_SMEM);
        attr_done = true;
    }

    int nblk = (n + 255) / 256;
    int gblk = (n + 127) / 128;
    k_zero<<<512, 256>>>(out + (size_t)n*64, nb, nc);
    k_scatter<<<nblk, 256>>>(points, pcyl, binv, cinv, n);
    k_lin1<<<nblk, 256>>>(points, pcyl, cylidx, bevidx, binv, cinv, w1, n);
    k_stats<<<512, 256>>>((const float*)p_lin1, n, 64, 6, (float*)p_stats + 0);
    k_finalize<<<1, 128>>>(g1, b1, 64, invn, 0, 0);
    dim3 g2d(gblk, 2);
    k_lin2<<<g2d, 256, L2_SMEM>>>(w2, n);
    k_stats<<<512, 256>>>((const float*)p_lin2, n, 128, 7, (float*)p_stats + 128);
    k_finalize<<<1, 128>>>(g2, b2, 128, invn, 128, 128);
    k_cylmax<<<nblk, 256>>>(points, cylidx, n);
    dim3 cg(3, 64, 4);
    k_conv<<<cg, 256, CONV_SMEM>>>(wc);
    k_stats<<<512, 256>>>((const float*)p_conv, 4*512*48, 64, 6, (float*)p_stats + 384);
    k_finalize<<<1, 128>>>(gc, bc, 64, 1.0f/(float)(4*512*48), 384, 384);
    k_gather<<<nblk, 256>>>(points, cylidx, n);
    k_lin3<<<gblk, 256, L3_SMEM>>>(w3, n);
    k_stats<<<512, 256>>>((const float*)p_lin3, n, 64, 6, (float*)p_stats + 512);
    k_finalize<<<1, 128>>>(g3, b3, 64, invn, 512, 512);
    int vblk = (nb + 255) / 256;
    k_final<<<nblk + vblk, 256>>>(binv, bcoord, out, n, nb, nblk);
}

// round 7
// speedup vs baseline: 1.4547x; 1.4157x over previous
#include <cuda_runtime.h>
#include <math.h>

typedef unsigned long long ull;
typedef unsigned int uint;

// ---------------- problem constants ----------------
#define NPTS_MAX 200000
#define NB_MAX   220000
#define NC_MAX   98304
#define IMG_ELEMS (4*512*48*64)

#define CVS0 (6.2831853f/512.0f)
#define CVS1 0.125f
#define CR0  (-3.14159265f)
#define CR1  (-2.0f)

// ---------------- scratch ----------------
__device__ float d_lin1[(size_t)NPTS_MAX*64];
__device__ float d_lin2[(size_t)NPTS_MAX*128];
__device__ float d_lin3[(size_t)NPTS_MAX*64];
__device__ float d_dense[IMG_ELEMS];
__device__ float d_conv[IMG_ELEMS];
__device__ float d_bevsum[NB_MAX*4];
__device__ float d_cylsum[NC_MAX*4];
__device__ float d_stats[1024];
__device__ float d_bn[1024];  // lin1 a@0 c@64; lin2 a@128 c@256; conv a@384 c@448; lin3 a@512 c@576

// ---------------- helpers ----------------
__device__ __forceinline__ ull pk2(float v) {
    ull r; unsigned u = __float_as_uint(v);
    asm("mov.b64 %0, {%1, %1};" : "=l"(r) : "r"(u));
    return r;
}
__device__ __forceinline__ void ffma2(ull& d, ull a, ull b) {
    asm("fma.rn.f32x2 %0, %1, %2, %0;" : "+l"(d) : "l"(a), "l"(b));
}
__device__ __forceinline__ uint tf32(float f) {
    uint r; asm("cvt.rna.tf32.f32 %0, %1;" : "=r"(r) : "f"(f)); return r;
}
__device__ __forceinline__ void mma_tf32(float* c, uint a0, uint a1, uint a2, uint a3, uint b0, uint b1) {
    asm volatile("mma.sync.aligned.m16n8k8.row.col.f32.tf32.tf32.f32 "
                 "{%0,%1,%2,%3},{%4,%5,%6,%7},{%8,%9},{%0,%1,%2,%3};"
                 : "+f"(c[0]), "+f"(c[1]), "+f"(c[2]), "+f"(c[3])
                 : "r"(a0), "r"(a1), "r"(a2), "r"(a3), "r"(b0), "r"(b1));
}

// ---------------- utility kernels ----------------
__global__ void __launch_bounds__(256) k_zero(float* outbev, int nb, int nc) {
    size_t tid = (size_t)blockIdx.x * blockDim.x + threadIdx.x;
    size_t stride = (size_t)gridDim.x * blockDim.x;
    float4 z = make_float4(0.f, 0.f, 0.f, 0.f);
    float4* p = (float4*)d_dense;
    for (size_t i = tid; i < IMG_ELEMS/4; i += stride) p[i] = z;
    float4* q = (float4*)outbev;
    size_t obw = (size_t)nb * 16;
    for (size_t i = tid; i < obw; i += stride) q[i] = z;
    float4* bs = (float4*)d_bevsum;
    for (size_t i = tid; i < (size_t)nb; i += stride) bs[i] = z;
    float4* cs = (float4*)d_cylsum;
    for (size_t i = tid; i < (size_t)nc; i += stride) cs[i] = z;
    if (tid < 256) ((float4*)d_stats)[tid] = z;
}

__global__ void k_scatter(const float* __restrict__ pts, const float* __restrict__ pcyl,
                          const int* __restrict__ binv, const int* __restrict__ cinv, int n) {
    int i = blockIdx.x*blockDim.x + threadIdx.x;
    if (i >= n) return;
    float x = pts[(size_t)i*5+1], y = pts[(size_t)i*5+2], z = pts[(size_t)i*5+3];
    int bi = binv[i], ci = cinv[i];
    atomicAdd(&d_bevsum[bi*4+0], x);
    atomicAdd(&d_bevsum[bi*4+1], y);
    atomicAdd(&d_bevsum[bi*4+2], z);
    atomicAdd(&d_bevsum[bi*4+3], 1.0f);
    float p0 = pcyl[(size_t)i*3], p1 = pcyl[(size_t)i*3+1], p2 = pcyl[(size_t)i*3+2];
    atomicAdd(&d_cylsum[ci*4+0], p0);
    atomicAdd(&d_cylsum[ci*4+1], p1);
    atomicAdd(&d_cylsum[ci*4+2], p2);
    atomicAdd(&d_cylsum[ci*4+3], 1.0f);
}

__global__ void __launch_bounds__(256) k_lin1(
        const float* __restrict__ pts, const float* __restrict__ pcyl,
        const float* __restrict__ cylidx, const float* __restrict__ bevidx,
        const int* __restrict__ binv, const int* __restrict__ cinv,
        const float* __restrict__ w1, int n) {
    __shared__ float sw[16*64];
    for (int t = threadIdx.x; t < 1024; t += 256) { int o = t >> 4, k = t & 15; sw[k*64+o] = w1[t]; }
    __syncthreads();
    int i = blockIdx.x*256 + threadIdx.x;
    if (i >= n) return;
    float x = pts[(size_t)i*5+1], y = pts[(size_t)i*5+2], z = pts[(size_t)i*5+3], it = pts[(size_t)i*5+4];
    float phi = pcyl[(size_t)i*3], zc = pcyl[(size_t)i*3+1], rho = pcyl[(size_t)i*3+2];
    float bix = bevidx[2*(size_t)i], biy = bevidx[2*(size_t)i+1];
    float cix = cylidx[2*(size_t)i], ciy = cylidx[2*(size_t)i+1];
    int bi = binv[i], ci = cinv[i];
    float bcnt = d_bevsum[bi*4+3];
    float bmx = d_bevsum[bi*4]/bcnt, bmy = d_bevsum[bi*4+1]/bcnt;
    float ccnt = d_cylsum[ci*4+3];
    float cm0 = d_cylsum[ci*4]/ccnt, cm1 = d_cylsum[ci*4+1]/ccnt;
    float f[16];
    f[0]=x; f[1]=y; f[2]=z; f[3]=phi; f[4]=zc; f[5]=rho;
    f[6] = x - ((floorf(bix)+0.5f)*0.32f + 0.0f);
    f[7] = y - ((floorf(biy)+0.5f)*0.32f + (-40.0f));
    f[8] = phi - ((floorf(cix)+0.5f)*CVS0 + CR0);
    f[9] = zc  - ((floorf(ciy)+0.5f)*CVS1 + CR1);
    f[10]= x - bmx; f[11]= y - bmy;
    f[12]= phi - cm0; f[13]= zc - cm1;
    f[14]= sqrtf(x*x + y*y + z*z);
    f[15]= it;
    ull acc[32];
    #pragma unroll
    for (int o = 0; o < 32; o++) acc[o] = 0ULL;
    #pragma unroll
    for (int k = 0; k < 16; k++) {
        ull v = pk2(f[k]);
        const ulonglong2* wr = (const ulonglong2*)&sw[k*64];
        #pragma unroll
        for (int m = 0; m < 16; m++) {
            ulonglong2 w = wr[m];
            ffma2(acc[2*m], v, w.x); ffma2(acc[2*m+1], v, w.y);
        }
    }
    ulonglong2* op = (ulonglong2*)&d_lin1[(size_t)i*64];
    #pragma unroll
    for (int m = 0; m < 16; m++) op[m] = make_ulonglong2(acc[2*m], acc[2*m+1]);
}

__global__ void k_stats(const float* __restrict__ data, int rows, int C, int shift, float* __restrict__ out) {
    int tid = threadIdx.x;
    int c = tid & (C-1);
    int sub = tid >> shift;
    int rpb = 256 >> shift;
    float s = 0.f, s2 = 0.f;
    for (long r = (long)blockIdx.x*rpb + sub; r < rows; r += (long)gridDim.x*rpb) {
        float v = data[(size_t)r*C + c];
        s += v; s2 += v*v;
    }
    __shared__ float sh[512];
    sh[tid] = s; sh[256+tid] = s2;
    __syncthreads();
    if (sub == 0) {
        for (int j = 1; j < rpb; j++) { s += sh[j*C + c]; s2 += sh[256 + j*C + c]; }
        atomicAdd(&out[c], s);
        atomicAdd(&out[C+c], s2);
    }
}

__global__ void k_finalize(const float* __restrict__ g, const float* __restrict__ b,
                           int C, float invn, int sbase, int bbase) {
    int c = threadIdx.x;
    if (c < C) {
        float m = d_stats[sbase+c]*invn;
        float v = d_stats[sbase+C+c]*invn - m*m;
        float a = g[c]*rsqrtf(v + 1e-3f);
        d_bn[bbase+c]   = a;
        d_bn[bbase+C+c] = b[c] - m*a;
    }
}

// ---------------- lin2: tf32 MMA GEMM  [N,64] @ [64,128] ----------------
#define L2_SMEM (17408*4)
__global__ void __launch_bounds__(256) k_lin2(const float* __restrict__ w2, int n) {
    extern __shared__ float dsm[];
    float* s_a = dsm;                // [p][k] pitch 68
    float* s_b = dsm + 128*68;       // [k][o] pitch 136
    __shared__ float sa[64], sc[64];
    int tid = threadIdx.x;
    if (tid < 64) { sa[tid] = d_bn[tid]; sc[tid] = d_bn[64+tid]; }
    for (int t = tid; t < 8192; t += 256) {
        int o = t >> 6, k = t & 63;
        s_b[k*136 + o] = __uint_as_float(tf32(w2[t]));
    }
    __syncthreads();
    int pbase = blockIdx.x*128;
    for (int idx = tid; idx < 128*16; idx += 256) {
        int lp = idx >> 4, kq = idx & 15;
        int p = pbase + lp, k = kq*4;
        float4 v = make_float4(0.f,0.f,0.f,0.f);
        if (p < n) v = *(const float4*)&d_lin1[(size_t)p*64 + k];
        uint4 tv;
        tv.x = tf32(fmaxf(fmaf(v.x, sa[k+0], sc[k+0]), 0.f));
        tv.y = tf32(fmaxf(fmaf(v.y, sa[k+1], sc[k+1]), 0.f));
        tv.z = tf32(fmaxf(fmaf(v.z, sa[k+2], sc[k+2]), 0.f));
        tv.w = tf32(fmaxf(fmaf(v.w, sa[k+3], sc[k+3]), 0.f));
        *(uint4*)&s_a[lp*68 + k] = tv;
    }
    __syncthreads();
    int wid = tid >> 5, lane = tid & 31;
    int g = lane >> 2, tg = lane & 3;
    int m0 = wid*16;
    const uint* ua = (const uint*)s_a;
    const uint* ub = (const uint*)s_b;
    float c[16][4];
    #pragma unroll
    for (int nt = 0; nt < 16; nt++)
        #pragma unroll
        for (int j = 0; j < 4; j++) c[nt][j] = 0.f;
    #pragma unroll
    for (int kc = 0; kc < 8; kc++) {
        int k0 = kc*8;
        // A fragment: a0=(g,tg) a1=(g+8,tg) a2=(g,tg+4) a3=(g+8,tg+4)
        uint a0 = ua[(m0+g)*68   + k0 + tg];
        uint a1 = ua[(m0+g+8)*68 + k0 + tg];
        uint a2 = ua[(m0+g)*68   + k0 + tg + 4];
        uint a3 = ua[(m0+g+8)*68 + k0 + tg + 4];
        #pragma unroll
        for (int nt = 0; nt < 16; nt++) {
            // B fragment: b0=(k=tg, n=g) b1=(k=tg+4, n=g)
            uint b0 = ub[(k0+tg)*136   + nt*8 + g];
            uint b1 = ub[(k0+tg+4)*136 + nt*8 + g];
            mma_tf32(c[nt], a0, a1, a2, a3, b0, b1);
        }
    }
    __syncthreads();
    float* stage = dsm;              // [p][o] pitch 132
    #pragma unroll
    for (int nt = 0; nt < 16; nt++) {
        int n0 = nt*8 + tg*2;
        *(float2*)&stage[(m0+g)*132   + n0] = make_float2(c[nt][0], c[nt][1]);
        *(float2*)&stage[(m0+g+8)*132 + n0] = make_float2(c[nt][2], c[nt][3]);
    }
    __syncthreads();
    for (int idx = tid; idx < 128*32; idx += 256) {
        int lp = idx >> 5, q = idx & 31;
        int p = pbase + lp;
        if (p < n)
            *(float4*)&d_lin2[(size_t)p*128 + q*4] = *(const float4*)&stage[lp*132 + q*4];
    }
}

// segment-max of bn_relu(lin2[:, :64]) into dense image
__global__ void k_cylmax(const float* __restrict__ pts, const float* __restrict__ cylidx, int n) {
    __shared__ float sa[64], sc[64];
    if (threadIdx.x < 64) { sa[threadIdx.x] = d_bn[128+threadIdx.x]; sc[threadIdx.x] = d_bn[256+threadIdx.x]; }
    __syncthreads();
    int i = blockIdx.x*blockDim.x + threadIdx.x;
    if (i >= n) return;
    int b = (int)pts[(size_t)i*5];
    int iy = (int)floorf(cylidx[2*(size_t)i]);   iy = max(0, min(iy, 511));
    int ix = (int)floorf(cylidx[2*(size_t)i+1]); ix = max(0, min(ix, 47));
    unsigned* dst = (unsigned*)&d_dense[(((size_t)b*512 + iy)*48 + ix)*64];
    const float4* src = (const float4*)&d_lin2[(size_t)i*128];
    #pragma unroll
    for (int j = 0; j < 16; j++) {
        float4 v = src[j];
        int c = j*4;
        float r0 = fmaxf(fmaf(v.x, sa[c+0], sc[c+0]), 0.f);
        float r1 = fmaxf(fmaf(v.y, sa[c+1], sc[c+1]), 0.f);
        float r2 = fmaxf(fmaf(v.z, sa[c+2], sc[c+2]), 0.f);
        float r3 = fmaxf(fmaf(v.w, sa[c+3], sc[c+3]), 0.f);
        atomicMax(dst+c+0, __float_as_uint(r0));
        atomicMax(dst+c+1, __float_as_uint(r1));
        atomicMax(dst+c+2, __float_as_uint(r2));
        atomicMax(dst+c+3, __float_as_uint(r3));
    }
}

// 3x3 SAME conv, 64->64 (f32x2, weights resident)
#define CTX 16
#define CTY 8
#define HPOS ((CTY+2)*(CTX+2))
#define WPITCH 68
#define IPITCH 65
#define CONV_SMEM ((576*WPITCH + HPOS*IPITCH)*4)
__global__ void __launch_bounds__(256) k_conv(const float* __restrict__ wc) {
    extern __shared__ float dsm[];
    float* s_w  = dsm;
    float* s_in = dsm + 576*WPITCH;
    int x0 = blockIdx.x*CTX, y0 = blockIdx.y*CTY, bb = blockIdx.z;
    int tid = threadIdx.x;
    for (int t = tid; t < 36864; t += 256) {
        int f = t / 576, r = t - f*576;
        s_w[r*WPITCH + f] = wc[t];
    }
    for (int idx = tid; idx < HPOS*16; idx += 256) {
        int pos = idx >> 4, c4 = idx & 15;
        int hy = pos / (CTX+2), hx = pos - hy*(CTX+2);
        int gy = y0 + hy - 1, gx = x0 + hx - 1;
        float4 v = make_float4(0.f,0.f,0.f,0.f);
        if (gy >= 0 && gy < 512 && gx >= 0 && gx < 48)
            v = *(const float4*)&d_dense[(((size_t)bb*512 + gy)*48 + gx)*64 + c4*4];
        float* s = &s_in[pos*IPITCH + c4*4];
        s[0]=v.x; s[1]=v.y; s[2]=v.z; s[3]=v.w;
    }
    __syncthreads();
    int fs = tid >> 5;
    int ps = tid & 31;
    int lyg = ps >> 4;
    int lx  = ps & 15;
    ull acc[4][4];
    #pragma unroll
    for (int r = 0; r < 4; r++)
        #pragma unroll
        for (int j = 0; j < 4; j++) acc[r][j] = 0ULL;
    for (int cin = 0; cin < 64; cin++) {
        ull pin[6][3];
        #pragma unroll
        for (int rr = 0; rr < 6; rr++)
            #pragma unroll
            for (int cc = 0; cc < 3; cc++)
                pin[rr][cc] = pk2(s_in[((lyg*4+rr)*(CTX+2) + lx + cc)*IPITCH + cin]);
        #pragma unroll
        for (int tap = 0; tap < 9; tap++) {
            int dy = tap/3, dx = tap - dy*3;
            const ulonglong2* wp = (const ulonglong2*)&s_w[(cin*9+tap)*WPITCH + fs*8];
            ulonglong2 w0 = wp[0], w1 = wp[1];
            #pragma unroll
            for (int r = 0; r < 4; r++) {
                ull v = pin[r+dy][dx];
                ffma2(acc[r][0], v, w0.x); ffma2(acc[r][1], v, w0.y);
                ffma2(acc[r][2], v, w1.x); ffma2(acc[r][3], v, w1.y);
            }
        }
    }
    int gx = x0 + lx;
    #pragma unroll
    for (int r = 0; r < 4; r++) {
        int gy = y0 + lyg*4 + r;
        ulonglong2* o = (ulonglong2*)&d_conv[(((size_t)bb*512 + gy)*48 + gx)*64 + fs*8];
        o[0] = make_ulonglong2(acc[r][0], acc[r][1]);
        o[1] = make_ulonglong2(acc[r][2], acc[r][3]);
    }
}

// ---------------- lin3: tf32 MMA GEMM [N,128] @ [128,64], gather inlined ----------------
#define L3_SMEM ((128*132 + 128*72)*4)
__global__ void __launch_bounds__(256) k_lin3(const float* __restrict__ pts,
        const float* __restrict__ cylidx, const float* __restrict__ w3, int n) {
    extern __shared__ float dsm[];
    float* s_a = dsm;                 // [p][k] pitch 132
    float* s_b = dsm + 128*132;       // [k][o] pitch 72
    __shared__ float pa[64], pc[64], ca[64], cs[64];
    __shared__ float s_w4[4][128];
    __shared__ int   s_o4[4][128];
    int tid = threadIdx.x;
    if (tid < 64) {
        pa[tid] = d_bn[192+tid]; pc[tid] = d_bn[320+tid];
        ca[tid] = d_bn[384+tid]; cs[tid] = d_bn[448+tid];
    }
    for (int t = tid; t < 8192; t += 256) {
        int o = t >> 7, k = t & 127;
        s_b[k*72 + o] = __uint_as_float(tf32(w3[t]));
    }
    int pbase = blockIdx.x*128;
    if (tid < 128) {
        int p = pbase + tid;
        int i = (p < n) ? p : (n-1);
        float yq = cylidx[2*(size_t)i], xq = cylidx[2*(size_t)i+1];
        int y0i = (int)floorf(yq); int y1i = min(y0i+1, 511); y0i = min(max(y0i,0), 511);
        int x0i = (int)floorf(xq); int x1i = min(x0i+1, 47);  x0i = min(max(x0i,0), 47);
        s_w4[0][tid] = ((float)x1i - xq)*((float)y1i - yq);
        s_w4[1][tid] = ((float)x1i - xq)*(yq - (float)y0i);
        s_w4[2][tid] = (xq - (float)x0i)*((float)y1i - yq);
        s_w4[3][tid] = (xq - (float)x0i)*(yq - (float)y0i);
        int b = (int)pts[(size_t)i*5];
        int base = b*512*48*64;
        s_o4[0][tid] = base + (y0i*48 + x0i)*64;
        s_o4[1][tid] = base + (y1i*48 + x0i)*64;
        s_o4[2][tid] = base + (y0i*48 + x1i)*64;
        s_o4[3][tid] = base + (y1i*48 + x1i)*64;
    }
    __syncthreads();
    for (int idx = tid; idx < 128*16; idx += 256) {
        int lp = idx >> 4, kq = idx & 15;
        int p = pbase + lp, k = kq*4;
        float4 v = make_float4(0.f,0.f,0.f,0.f);
        if (p < n) {
            v = *(const float4*)&d_lin2[(size_t)p*128 + 64 + k];
            v.x = fmaxf(fmaf(v.x, pa[k+0], pc[k+0]), 0.f);
            v.y = fmaxf(fmaf(v.y, pa[k+1], pc[k+1]), 0.f);
            v.z = fmaxf(fmaf(v.z, pa[k+2], pc[k+2]), 0.f);
            v.w = fmaxf(fmaf(v.w, pa[k+3], pc[k+3]), 0.f);
        }
        uint4 tv;
        tv.x = tf32(v.x); tv.y = tf32(v.y); tv.z = tf32(v.z); tv.w = tf32(v.w);
        *(uint4*)&s_a[lp*132 + k] = tv;
    }
    for (int idx = tid; idx < 128*16; idx += 256) {
        int lp = idx >> 4, kq = idx & 15;
        int p = pbase + lp, c = kq*4;
        float4 r = make_float4(0.f,0.f,0.f,0.f);
        if (p < n) {
            float wa = s_w4[0][lp], wb = s_w4[1][lp], wcw = s_w4[2][lp], wd = s_w4[3][lp];
            float4 av = *(const float4*)&d_conv[s_o4[0][lp] + c];
            float4 bv = *(const float4*)&d_conv[s_o4[1][lp] + c];
            float4 cv = *(const float4*)&d_conv[s_o4[2][lp] + c];
            float4 dv = *(const float4*)&d_conv[s_o4[3][lp] + c];
            r.x = wa*fmaxf(fmaf(av.x, ca[c+0], cs[c+0]),0.f) + wb*fmaxf(fmaf(bv.x, ca[c+0], cs[c+0]),0.f)
                + wcw*fmaxf(fmaf(cv.x, ca[c+0], cs[c+0]),0.f) + wd*fmaxf(fmaf(dv.x, ca[c+0], cs[c+0]),0.f);
            r.y = wa*fmaxf(fmaf(av.y, ca[c+1], cs[c+1]),0.f) + wb*fmaxf(fmaf(bv.y, ca[c+1], cs[c+1]),0.f)
                + wcw*fmaxf(fmaf(cv.y, ca[c+1], cs[c+1]),0.f) + wd*fmaxf(fmaf(dv.y, ca[c+1], cs[c+1]),0.f);
            r.z = wa*fmaxf(fmaf(av.z, ca[c+2], cs[c+2]),0.f) + wb*fmaxf(fmaf(bv.z, ca[c+2], cs[c+2]),0.f)
                + wcw*fmaxf(fmaf(cv.z, ca[c+2], cs[c+2]),0.f) + wd*fmaxf(fmaf(dv.z, ca[c+2], cs[c+2]),0.f);
            r.w = wa*fmaxf(fmaf(av.w, ca[c+3], cs[c+3]),0.f) + wb*fmaxf(fmaf(bv.w, ca[c+3], cs[c+3]),0.f)
                + wcw*fmaxf(fmaf(cv.w, ca[c+3], cs[c+3]),0.f) + wd*fmaxf(fmaf(dv.w, ca[c+3], cs[c+3]),0.f);
        }
        uint4 tv;
        tv.x = tf32(r.x); tv.y = tf32(r.y); tv.z = tf32(r.z); tv.w = tf32(r.w);
        *(uint4*)&s_a[lp*132 + 64 + c] = tv;
    }
    __syncthreads();
    int wid = tid >> 5, lane = tid & 31;
    int g = lane >> 2, tg = lane & 3;
    int m0 = wid*16;
    const uint* ua = (const uint*)s_a;
    const uint* ub = (const uint*)s_b;
    float c[8][4];
    #pragma unroll
    for (int nt = 0; nt < 8; nt++)
        #pragma unroll
        for (int j = 0; j < 4; j++) c[nt][j] = 0.f;
    #pragma unroll
    for (int kc = 0; kc < 16; kc++) {
        int k0 = kc*8;
        uint a0 = ua[(m0+g)*132   + k0 + tg];
        uint a1 = ua[(m0+g+8)*132 + k0 + tg];
        uint a2 = ua[(m0+g)*132   + k0 + tg + 4];
        uint a3 = ua[(m0+g+8)*132 + k0 + tg + 4];
        #pragma unroll
        for (int nt = 0; nt < 8; nt++) {
            uint b0 = ub[(k0+tg)*72   + nt*8 + g];
            uint b1 = ub[(k0+tg+4)*72 + nt*8 + g];
            mma_tf32(c[nt], a0, a1, a2, a3, b0, b1);
        }
    }
    __syncthreads();
    float* stage = dsm;              // [p][o] pitch 68
    #pragma unroll
    for (int nt = 0; nt < 8; nt++) {
        int n0 = nt*8 + tg*2;
        *(float2*)&stage[(m0+g)*68   + n0] = make_float2(c[nt][0], c[nt][1]);
        *(float2*)&stage[(m0+g+8)*68 + n0] = make_float2(c[nt][2], c[nt][3]);
    }
    __syncthreads();
    for (int idx = tid; idx < 128*16; idx += 256) {
        int lp = idx >> 4, q = idx & 15;
        int p = pbase + lp;
        if (p < n)
            *(float4*)&d_lin3[(size_t)p*64 + q*4] = *(const float4*)&stage[lp*68 + q*4];
    }
}

// final: bn_relu(lin3) -> out; atomicMax into bev_max; extra blocks do voxel coords
__global__ void k_final(const int* __restrict__ binv, const int* __restrict__ bcoord,
                        float* __restrict__ out, int n, int nb, int nblk) {
    if (blockIdx.x >= nblk) {
        int i = (blockIdx.x - nblk)*blockDim.x + threadIdx.x;
        if (i < nb) {
            int c = bcoord[i];
            int vb = c / 55000;
            int r  = c % 55000;
            int vx = r / 250;
            int vy = r % 250;
            float* o = out + (size_t)n*64 + (size_t)nb*64 + (size_t)i*4;
            o[0] = (float)vb; o[1] = 0.f; o[2] = (float)vy; o[3] = (float)vx;
        }
        return;
    }
    __shared__ float sa[64], sc[64];
    if (threadIdx.x < 64) { sa[threadIdx.x] = d_bn[512+threadIdx.x]; sc[threadIdx.x] = d_bn[576+threadIdx.x]; }
    __syncthreads();
    int i = blockIdx.x*blockDim.x + threadIdx.x;
    if (i >= n) return;
    int bi = binv[i];
    const float4* src = (const float4*)&d_lin3[(size_t)i*64];
    float4* dst = (float4*)(out + (size_t)i*64);
    unsigned* mx = (unsigned*)(out + (size_t)n*64 + (size_t)bi*64);
    #pragma unroll
    for (int j = 0; j < 16; j++) {
        float4 v = src[j];
        int c = j*4;
        float r0 = fmaxf(fmaf(v.x, sa[c+0], sc[c+0]), 0.f);
        float r1 = fmaxf(fmaf(v.y, sa[c+1], sc[c+1]), 0.f);
        float r2 = fmaxf(fmaf(v.z, sa[c+2], sc[c+2]), 0.f);
        float r3 = fmaxf(fmaf(v.w, sa[c+3], sc[c+3]), 0.f);
        dst[j] = make_float4(r0, r1, r2, r3);
        atomicMax(mx+c+0, __float_as_uint(r0));
        atomicMax(mx+c+1, __float_as_uint(r1));
        atomicMax(mx+c+2, __float_as_uint(r2));
        atomicMax(mx+c+3, __float_as_uint(r3));
    }
}

// ---------------- launcher ----------------
extern "C" void kernel_launch(void* const* d_in, const int* in_sizes, int n_in,
                              void* d_out, int out_size) {
    const float* points = (const float*)d_in[0];
    const float* pcyl   = (const float*)d_in[1];
    const float* cylidx = (const float*)d_in[2];
    const float* bevidx = (const float*)d_in[3];
    const float* w1 = (const float*)d_in[4];
    const float* g1 = (const float*)d_in[5];
    const float* b1 = (const float*)d_in[6];
    const float* w2 = (const float*)d_in[7];
    const float* g2 = (const float*)d_in[8];
    const float* b2 = (const float*)d_in[9];
    const float* wc = (const float*)d_in[10];
    const float* gc = (const float*)d_in[11];
    const float* bc = (const float*)d_in[12];
    const float* w3 = (const float*)d_in[13];
    const float* g3 = (const float*)d_in[14];
    const float* b3 = (const float*)d_in[15];
    const int* binv   = (const int*)d_in[16];
    const int* bcoord = (const int*)d_in[17];
    const int* cinv   = (const int*)d_in[18];

    int n  = in_sizes[0] / 5;
    int nb = in_sizes[17];
    int nc = in_sizes[19];
    float* out = (float*)d_out;
    float invn = 1.0f/(float)n;

    void *p_lin1, *p_lin2, *p_conv, *p_lin3, *p_stats;
    cudaGetSymbolAddress(&p_lin1, d_lin1);
    cudaGetSymbolAddress(&p_lin2, d_lin2);
    cudaGetSymbolAddress(&p_conv, d_conv);
    cudaGetSymbolAddress(&p_lin3, d_lin3);
    cudaGetSymbolAddress(&p_stats, d_stats);

    static bool attr_done = false;
    if (!attr_done) {
        cudaFuncSetAttribute(k_conv, cudaFuncAttributeMaxDynamicSharedMemorySize, CONV_SMEM);
        cudaFuncSetAttribute(k_lin2, cudaFuncAttributeMaxDynamicSharedMemorySize, L2_SMEM);
        cudaFuncSetAttribute(k_lin3, cudaFuncAttributeMaxDynamicSharedMemorySize, L3_SMEM);
        attr_done = true;
    }

    int nblk = (n + 255) / 256;
    int gblk = (n + 127) / 128;
    k_zero<<<512, 256>>>(out + (size_t)n*64, nb, nc);
    k_scatter<<<nblk, 256>>>(points, pcyl, binv, cinv, n);
    k_lin1<<<nblk, 256>>>(points, pcyl, cylidx, bevidx, binv, cinv, w1, n);
    k_stats<<<512, 256>>>((const float*)p_lin1, n, 64, 6, (float*)p_stats + 0);
    k_finalize<<<1, 128>>>(g1, b1, 64, invn, 0, 0);
    k_lin2<<<gblk, 256, L2_SMEM>>>(w2, n);
    k_stats<<<512, 256>>>((const float*)p_lin2, n, 128, 7, (float*)p_stats + 128);
    k_finalize<<<1, 128>>>(g2, b2, 128, invn, 128, 128);
    k_cylmax<<<nblk, 256>>>(points, cylidx, n);
    dim3 cg(3, 64, 4);
    k_conv<<<cg, 256, CONV_SMEM>>>(wc);
    k_stats<<<512, 256>>>((const float*)p_conv, 4*512*48, 64, 6, (float*)p_stats + 384);
    k_finalize<<<1, 128>>>(gc, bc, 64, 1.0f/(float)(4*512*48), 384, 384);
    k_lin3<<<gblk, 256, L3_SMEM>>>(points, cylidx, w3, n);
    k_stats<<<512, 256>>>((const float*)p_lin3, n, 64, 6, (float*)p_stats + 512);
    k_finalize<<<1, 128>>>(g3, b3, 64, invn, 512, 512);
    int vblk = (nb + 255) / 256;
    k_final<<<nblk + vblk, 256>>>(binv, bcoord, out, n, nb, nblk);
}